// round 1
// baseline (speedup 1.0000x reference)
#include <cuda_runtime.h>

// Problem constants
#define Bn  16
#define Cn  32
#define Nn  128
#define Tn  12
#define COn 64
#define NT  (Nn * Tn)          // 1536 floats per (b,i,j) row of A; also per x channel-slice
#define NT4 (NT / 4)           // 384 float4

// Scratch: h = concat([x1, x2], channel axis) -> [B][2C][N*T] = 6.3 MB
__device__ float g_h[(size_t)Bn * 2 * Cn * NT];

// ---------------------------------------------------------------------------
// Kernel 1: fused order-1 + order-2 propagation.
// One CTA per (b, i). 384 threads; thread t owns output elements [4t, 4t+4)
// of the 1536-element (k,l) plane. Since 4 | 12, each float4 has fixed k and
// l0 = (4t) % 12 in {0,4,8} -> the x multiplier x[j, l0..l0+3] is one LDS.128.
// Phase 1: x1 = x^T A (stream A once). Phase 2: x2 = x1^T A (re-stream A,
// ideally from L2 since the slice is hot).
// ---------------------------------------------------------------------------
__global__ __launch_bounds__(NT4) void prop_kernel(const float* __restrict__ x,
                                                   const float* __restrict__ A) {
    __shared__ float4 xs[NT4];    // x[b,i,:,:]  as [j*3 + l0/4]
    __shared__ float4 x1s[NT4];   // x1[b,i,:,:] same layout

    const int bc = blockIdx.x;            // b*C + i
    const int t  = threadIdx.x;           // 0..383
    const int lq = t % 3;                 // l0 / 4

    const float4* __restrict__ xp = (const float4*)(x + (size_t)bc * NT);
    const float4* __restrict__ Ap = (const float4*)(A + (size_t)bc * Nn * NT);

    xs[t] = xp[t];
    __syncthreads();

    // ---- Phase 1: x1[k,l] = sum_j x[j,l] * A[j,k,l] ----
    float4 acc1 = make_float4(0.f, 0.f, 0.f, 0.f);
#pragma unroll 8
    for (int j = 0; j < Nn; ++j) {
        float4 a  = Ap[j * NT4 + t];
        float4 xv = xs[j * 3 + lq];
        acc1.x = fmaf(a.x, xv.x, acc1.x);
        acc1.y = fmaf(a.y, xv.y, acc1.y);
        acc1.z = fmaf(a.z, xv.z, acc1.z);
        acc1.w = fmaf(a.w, xv.w, acc1.w);
    }
    x1s[t] = acc1;
    __syncthreads();

    // ---- Phase 2: x2[k,l] = sum_j x1[j,l] * A[j,k,l] ----
    float4 acc2 = make_float4(0.f, 0.f, 0.f, 0.f);
#pragma unroll 8
    for (int j = 0; j < Nn; ++j) {
        float4 a  = Ap[j * NT4 + t];
        float4 xv = x1s[j * 3 + lq];
        acc2.x = fmaf(a.x, xv.x, acc2.x);
        acc2.y = fmaf(a.y, xv.y, acc2.y);
        acc2.z = fmaf(a.z, xv.z, acc2.z);
        acc2.w = fmaf(a.w, xv.w, acc2.w);
    }

    // ---- Write h: h[b, i, :] = x1 ; h[b, C+i, :] = x2 ----
    const int b = bc / Cn;
    const int i = bc % Cn;
    float4* h1 = (float4*)(g_h + ((size_t)b * 2 * Cn + i) * NT);
    float4* h2 = (float4*)(g_h + ((size_t)b * 2 * Cn + Cn + i) * NT);
    h1[t] = acc1;
    h2[t] = acc2;
}

// ---------------------------------------------------------------------------
// Kernel 2: 1x1 conv channel mix.  out[b,o,col] = sum_c W[o,c]*h[b,c,col] + bias[o]
// Grid: (B * NT/128) blocks, 128 threads; each thread owns one (n,l) column,
// keeps the 64-channel h column in registers, streams W from SMEM as float4.
// ---------------------------------------------------------------------------
#define COLS_PER_BLK 128
#define NCOLBLK (NT / COLS_PER_BLK)   // 12

__global__ __launch_bounds__(COLS_PER_BLK) void mix_kernel(const float* __restrict__ W,
                                                           const float* __restrict__ bias,
                                                           float* __restrict__ out) {
    __shared__ float4 Ws[COn * (2 * Cn) / 4];   // 1024 float4 = 16 KB
    __shared__ float  bs[COn];

    const int t   = threadIdx.x;
    const int blk = blockIdx.x;
    const int b   = blk / NCOLBLK;
    const int col = (blk % NCOLBLK) * COLS_PER_BLK + t;

    const float4* W4 = (const float4*)W;
#pragma unroll
    for (int s = 0; s < 8; ++s)
        Ws[t + COLS_PER_BLK * s] = W4[t + COLS_PER_BLK * s];
    if (t < COn) bs[t] = bias[t];
    __syncthreads();

    // h column into registers
    const float* hp = g_h + (size_t)b * 2 * Cn * NT + col;
    float hreg[2 * Cn];
#pragma unroll
    for (int c = 0; c < 2 * Cn; ++c)
        hreg[c] = hp[(size_t)c * NT];

    float* op = out + (size_t)b * COn * NT + col;
#pragma unroll 4
    for (int o = 0; o < COn; ++o) {
        float acc = bs[o];
#pragma unroll
        for (int c4 = 0; c4 < (2 * Cn) / 4; ++c4) {
            float4 w = Ws[o * ((2 * Cn) / 4) + c4];
            acc = fmaf(w.x, hreg[c4 * 4 + 0], acc);
            acc = fmaf(w.y, hreg[c4 * 4 + 1], acc);
            acc = fmaf(w.z, hreg[c4 * 4 + 2], acc);
            acc = fmaf(w.w, hreg[c4 * 4 + 3], acc);
        }
        op[(size_t)o * NT] = acc;
    }
}

// ---------------------------------------------------------------------------
extern "C" void kernel_launch(void* const* d_in, const int* in_sizes, int n_in,
                              void* d_out, int out_size) {
    const float* x    = (const float*)d_in[0];   // [B,C,N,T]
    const float* A    = (const float*)d_in[1];   // [B,C,N,N,T]
    const float* W    = (const float*)d_in[2];   // [C_OUT, 2C]
    const float* bias = (const float*)d_in[3];   // [C_OUT]
    float* out = (float*)d_out;                  // [B,C_OUT,N,T]

    prop_kernel<<<Bn * Cn, NT4>>>(x, A);
    mix_kernel<<<Bn * NCOLBLK, COLS_PER_BLK>>>(W, bias, out);
}